// round 6
// baseline (speedup 1.0000x reference)
#include <cuda_runtime.h>

// Allocation-free scratch: per-block partials + completion ticket.
#define MAX_BLOCKS 4096
__device__ double       g_part[MAX_BLOCKS];
__device__ unsigned int g_count = 0;

__device__ __forceinline__ float giou_one(
    float px1, float py1, float px2, float py2, float pz1, float pz2,
    float tx1, float ty1, float tx2, float ty2, float tz1, float tz2)
{
    float vol1 = (px2 - px1) * (py2 - py1) * (pz2 - pz1);
    float vol2 = (tx2 - tx1) * (ty2 - ty1) * (tz2 - tz1);

    float ix = fmaxf(fminf(px2, tx2) - fmaxf(px1, tx1), 0.0f);
    float iy = fmaxf(fminf(py2, ty2) - fmaxf(py1, ty1), 0.0f);
    float iz = fmaxf(fminf(pz2, tz2) - fmaxf(pz1, tz1), 0.0f);
    float inter = ix * iy * iz;
    float uni   = vol1 + vol2 - inter;
    float iou   = inter / uni;

    float ex = fmaxf(fmaxf(px2, tx2) - fminf(px1, tx1), 0.0f);
    float ey = fmaxf(fmaxf(py2, ty2) - fminf(py1, ty1), 0.0f);
    float ez = fmaxf(fmaxf(pz2, tz2) - fminf(pz1, tz1), 0.0f);
    float enc = ex * ey * ez + 1e-7f;

    return iou - (enc - uni) / enc;
}

__device__ __forceinline__ float giou_pair(
    const float4* __restrict__ p4, const float4* __restrict__ t4, long i)
{
    float4 a0 = p4[3L * i + 0];
    float4 a1 = p4[3L * i + 1];
    float4 a2 = p4[3L * i + 2];
    float4 b0 = t4[3L * i + 0];
    float4 b1 = t4[3L * i + 1];
    float4 b2 = t4[3L * i + 2];

    float r = giou_one(a0.x, a0.y, a0.z, a0.w, a1.x, a1.y,
                       b0.x, b0.y, b0.z, b0.w, b1.x, b1.y);
    r      += giou_one(a1.z, a1.w, a2.x, a2.y, a2.z, a2.w,
                       b1.z, b1.w, b2.x, b2.y, b2.z, b2.w);
    return r;
}

// Single fused kernel: one exact wave, grid-stride (unrolled x2), block
// reduce, last-block final reduction. Row layout: [x1,y1,x2,y2,z1,z2].
__global__ void __launch_bounds__(256) k_giou(
    const float4* __restrict__ p4, const float4* __restrict__ t4,
    int npairs, int nboxes, float* __restrict__ out)
{
    int stride = gridDim.x * blockDim.x;
    int tid    = blockIdx.x * blockDim.x + threadIdx.x;
    float s = 0.0f;

    // unrolled-by-2 grid-stride: 12 independent LDG.128 in flight
    int i = tid;
    for (; i + stride < npairs; i += 2 * stride) {
        s += giou_pair(p4, t4, i);
        s += giou_pair(p4, t4, i + stride);
    }
    if (i < npairs)
        s += giou_pair(p4, t4, i);

    // odd tail box (not hit for N=4M, kept for generality)
    if ((nboxes & 1) && tid == 0) {
        const float* pf = (const float*)p4;
        const float* tf = (const float*)t4;
        long b = (long)(nboxes - 1) * 6;
        s += giou_one(pf[b+0], pf[b+1], pf[b+2], pf[b+3], pf[b+4], pf[b+5],
                      tf[b+0], tf[b+1], tf[b+2], tf[b+3], tf[b+4], tf[b+5]);
    }

    // ---- block reduce (float) ----
    #pragma unroll
    for (int o = 16; o > 0; o >>= 1)
        s += __shfl_down_sync(0xffffffffu, s, o);

    __shared__ float  ws[8];
    __shared__ bool   is_last;
    int lane = threadIdx.x & 31;
    int w    = threadIdx.x >> 5;
    if (lane == 0) ws[w] = s;
    __syncthreads();

    if (threadIdx.x == 0) {
        float bs = 0.0f;
        #pragma unroll
        for (int j = 0; j < 8; j++) bs += ws[j];
        g_part[blockIdx.x] = (double)bs;
        __threadfence();
        unsigned int t = atomicAdd(&g_count, 1u);
        is_last = (t == gridDim.x - 1);
    }
    __syncthreads();

    // ---- last block: final reduction over all partials ----
    if (is_last) {
        double d = 0.0;
        for (int j = threadIdx.x; j < gridDim.x; j += blockDim.x)
            d += g_part[j];

        #pragma unroll
        for (int o = 16; o > 0; o >>= 1)
            d += __shfl_down_sync(0xffffffffu, d, o);

        __shared__ double wd[8];
        if (lane == 0) wd[w] = d;
        __syncthreads();
        if (threadIdx.x == 0) {
            double tot = 0.0;
            #pragma unroll
            for (int j = 0; j < 8; j++) tot += wd[j];
            out[0] = (float)(-tot);   // loss = -sum(giou)
            g_count = 0;              // reset for next graph replay
        }
    }
}

extern "C" void kernel_launch(void* const* d_in, const int* in_sizes, int n_in,
                              void* d_out, int out_size)
{
    const float* pred = (const float*)d_in[0];
    const float* targ = (const float*)d_in[1];
    float* out = (float*)d_out;

    int nboxes = in_sizes[0] / 6;
    int npairs = nboxes / 2;

    const int TPB = 256;

    // Exact one wave: resident blocks/SM * SM count (host query, capture-safe,
    // deterministic; cached so replays are identical).
    static int blocks_cached = 0;
    if (blocks_cached == 0) {
        int maxb = 0;
        cudaOccupancyMaxActiveBlocksPerMultiprocessor(&maxb, k_giou, TPB, 0);
        if (maxb < 1) maxb = 4;
        int sms = 148;
        cudaDeviceGetAttribute(&sms, cudaDevAttrMultiProcessorCount, 0);
        long w = (long)maxb * sms;
        blocks_cached = (w > MAX_BLOCKS) ? MAX_BLOCKS : (int)w;
    }
    int blocks = blocks_cached;
    int needed = (npairs + TPB - 1) / TPB;
    if (blocks > needed) blocks = needed;
    if (blocks < 1) blocks = 1;

    k_giou<<<blocks, TPB>>>((const float4*)pred, (const float4*)targ,
                            npairs, nboxes, out);
}

// round 7
// speedup vs baseline: 1.0434x; 1.0434x over previous
#include <cuda_runtime.h>

// Allocation-free scratch: per-block partials + completion ticket.
#define MAX_BLOCKS 4096
__device__ double       g_part[MAX_BLOCKS];
__device__ unsigned int g_count = 0;

__device__ __forceinline__ float giou_one(
    float px1, float py1, float px2, float py2, float pz1, float pz2,
    float tx1, float ty1, float tx2, float ty2, float tz1, float tz2)
{
    float vol1 = (px2 - px1) * (py2 - py1) * (pz2 - pz1);
    float vol2 = (tx2 - tx1) * (ty2 - ty1) * (tz2 - tz1);

    float ix = fmaxf(fminf(px2, tx2) - fmaxf(px1, tx1), 0.0f);
    float iy = fmaxf(fminf(py2, ty2) - fmaxf(py1, ty1), 0.0f);
    float iz = fmaxf(fminf(pz2, tz2) - fmaxf(pz1, tz1), 0.0f);
    float inter = ix * iy * iz;
    float uni   = vol1 + vol2 - inter;
    float iou   = inter / uni;

    float ex = fmaxf(fmaxf(px2, tx2) - fminf(px1, tx1), 0.0f);
    float ey = fmaxf(fmaxf(py2, ty2) - fminf(py1, ty1), 0.0f);
    float ez = fmaxf(fmaxf(pz2, tz2) - fminf(pz1, tz1), 0.0f);
    float enc = ex * ey * ez + 1e-7f;

    return iou - (enc - uni) / enc;
}

// Compute both boxes of one pair from 6 preloaded float4s.
__device__ __forceinline__ float giou_from_regs(
    float4 a0, float4 a1, float4 a2, float4 b0, float4 b1, float4 b2)
{
    float r = giou_one(a0.x, a0.y, a0.z, a0.w, a1.x, a1.y,
                       b0.x, b0.y, b0.z, b0.w, b1.x, b1.y);
    r      += giou_one(a1.z, a1.w, a2.x, a2.y, a2.z, a2.w,
                       b1.z, b1.w, b2.x, b2.y, b2.z, b2.w);
    return r;
}

// Single fused kernel: one exact wave, grid-stride unrolled x4 with
// pointer-stepping and 4 independent accumulators. Block reduce +
// last-block final reduction. Row layout: [x1,y1,x2,y2,z1,z2].
__global__ void __launch_bounds__(256) k_giou(
    const float4* __restrict__ p4, const float4* __restrict__ t4,
    int npairs, int nboxes, float* __restrict__ out)
{
    int stride = gridDim.x * blockDim.x;        // pairs per grid step
    int tid    = blockIdx.x * blockDim.x + threadIdx.x;
    long step  = 3L * stride;                   // float4s per grid step

    float s0 = 0.0f, s1 = 0.0f, s2 = 0.0f, s3 = 0.0f;

    const float4* pp = p4 + 3L * tid;
    const float4* tp = t4 + 3L * tid;

    int i = tid;
    // ---- unrolled x4: 24 independent LDG.128 issued before compute ----
    for (; i + 3 * stride < npairs; i += 4 * stride) {
        float4 pa0 = pp[0],        pa1 = pp[1],        pa2 = pp[2];
        float4 pb0 = pp[step],     pb1 = pp[step+1],   pb2 = pp[step+2];
        float4 pc0 = pp[2*step],   pc1 = pp[2*step+1], pc2 = pp[2*step+2];
        float4 pd0 = pp[3*step],   pd1 = pp[3*step+1], pd2 = pp[3*step+2];
        float4 ta0 = tp[0],        ta1 = tp[1],        ta2 = tp[2];
        float4 tb0 = tp[step],     tb1 = tp[step+1],   tb2 = tp[step+2];
        float4 tc0 = tp[2*step],   tc1 = tp[2*step+1], tc2 = tp[2*step+2];
        float4 td0 = tp[3*step],   td1 = tp[3*step+1], td2 = tp[3*step+2];

        s0 += giou_from_regs(pa0, pa1, pa2, ta0, ta1, ta2);
        s1 += giou_from_regs(pb0, pb1, pb2, tb0, tb1, tb2);
        s2 += giou_from_regs(pc0, pc1, pc2, tc0, tc1, tc2);
        s3 += giou_from_regs(pd0, pd1, pd2, td0, td1, td2);

        pp += 4 * step;
        tp += 4 * step;
    }
    // ---- remainder (0..3 pairs) ----
    for (; i < npairs; i += stride) {
        float4 pa0 = pp[0], pa1 = pp[1], pa2 = pp[2];
        float4 ta0 = tp[0], ta1 = tp[1], ta2 = tp[2];
        s0 += giou_from_regs(pa0, pa1, pa2, ta0, ta1, ta2);
        pp += step;
        tp += step;
    }

    float s = (s0 + s1) + (s2 + s3);

    // odd tail box (not hit for N=4M, kept for generality)
    if ((nboxes & 1) && tid == 0) {
        const float* pf = (const float*)p4;
        const float* tf = (const float*)t4;
        long b = (long)(nboxes - 1) * 6;
        s += giou_one(pf[b+0], pf[b+1], pf[b+2], pf[b+3], pf[b+4], pf[b+5],
                      tf[b+0], tf[b+1], tf[b+2], tf[b+3], tf[b+4], tf[b+5]);
    }

    // ---- block reduce (float) ----
    #pragma unroll
    for (int o = 16; o > 0; o >>= 1)
        s += __shfl_down_sync(0xffffffffu, s, o);

    __shared__ float  ws[8];
    __shared__ bool   is_last;
    int lane = threadIdx.x & 31;
    int w    = threadIdx.x >> 5;
    if (lane == 0) ws[w] = s;
    __syncthreads();

    if (threadIdx.x == 0) {
        float bs = 0.0f;
        #pragma unroll
        for (int j = 0; j < 8; j++) bs += ws[j];
        g_part[blockIdx.x] = (double)bs;
        __threadfence();
        unsigned int t = atomicAdd(&g_count, 1u);
        is_last = (t == gridDim.x - 1);
    }
    __syncthreads();

    // ---- last block: final reduction over all partials ----
    if (is_last) {
        double d = 0.0;
        for (int j = threadIdx.x; j < gridDim.x; j += blockDim.x)
            d += g_part[j];

        #pragma unroll
        for (int o = 16; o > 0; o >>= 1)
            d += __shfl_down_sync(0xffffffffu, d, o);

        __shared__ double wd[8];
        if (lane == 0) wd[w] = d;
        __syncthreads();
        if (threadIdx.x == 0) {
            double tot = 0.0;
            #pragma unroll
            for (int j = 0; j < 8; j++) tot += wd[j];
            out[0] = (float)(-tot);   // loss = -sum(giou)
            g_count = 0;              // reset for next graph replay
        }
    }
}

extern "C" void kernel_launch(void* const* d_in, const int* in_sizes, int n_in,
                              void* d_out, int out_size)
{
    const float* pred = (const float*)d_in[0];
    const float* targ = (const float*)d_in[1];
    float* out = (float*)d_out;

    int nboxes = in_sizes[0] / 6;
    int npairs = nboxes / 2;

    const int TPB = 256;

    // Exact one wave: resident blocks/SM * SM count (host query, cached).
    static int blocks_cached = 0;
    if (blocks_cached == 0) {
        int maxb = 0;
        cudaOccupancyMaxActiveBlocksPerMultiprocessor(&maxb, k_giou, TPB, 0);
        if (maxb < 1) maxb = 2;
        int sms = 148;
        cudaDeviceGetAttribute(&sms, cudaDevAttrMultiProcessorCount, 0);
        long w = (long)maxb * sms;
        blocks_cached = (w > MAX_BLOCKS) ? MAX_BLOCKS : (int)w;
    }
    int blocks = blocks_cached;
    int needed = (npairs + TPB - 1) / TPB;
    if (blocks > needed) blocks = needed;
    if (blocks < 1) blocks = 1;

    k_giou<<<blocks, TPB>>>((const float4*)pred, (const float4*)targ,
                            npairs, nboxes, out);
}

// round 8
// speedup vs baseline: 1.1105x; 1.0643x over previous
#include <cuda_runtime.h>

// Allocation-free scratch: per-block partials, completion ticket, work ticket.
#define MAX_BLOCKS 4096
__device__ double       g_part[MAX_BLOCKS];
__device__ unsigned int g_count = 0;
__device__ unsigned int g_work  = 0;

// Pairs per chunk: 2 pairs per thread at 256 threads.
#define TPB        256
#define CHUNK_PAIRS (2 * TPB)

__device__ __forceinline__ float giou_one(
    float px1, float py1, float px2, float py2, float pz1, float pz2,
    float tx1, float ty1, float tx2, float ty2, float tz1, float tz2)
{
    float vol1 = (px2 - px1) * (py2 - py1) * (pz2 - pz1);
    float vol2 = (tx2 - tx1) * (ty2 - ty1) * (tz2 - tz1);

    float ix = fmaxf(fminf(px2, tx2) - fmaxf(px1, tx1), 0.0f);
    float iy = fmaxf(fminf(py2, ty2) - fmaxf(py1, ty1), 0.0f);
    float iz = fmaxf(fminf(pz2, tz2) - fmaxf(pz1, tz1), 0.0f);
    float inter = ix * iy * iz;
    float uni   = vol1 + vol2 - inter;
    float iou   = inter / uni;

    float ex = fmaxf(fmaxf(px2, tx2) - fminf(px1, tx1), 0.0f);
    float ey = fmaxf(fmaxf(py2, ty2) - fminf(py1, ty1), 0.0f);
    float ez = fmaxf(fmaxf(pz2, tz2) - fminf(pz1, tz1), 0.0f);
    float enc = ex * ey * ez + 1e-7f;

    return iou - (enc - uni) / enc;
}

__device__ __forceinline__ float giou_pair(
    const float4* __restrict__ p4, const float4* __restrict__ t4, long i)
{
    float4 a0 = p4[3L * i + 0];
    float4 a1 = p4[3L * i + 1];
    float4 a2 = p4[3L * i + 2];
    float4 b0 = t4[3L * i + 0];
    float4 b1 = t4[3L * i + 1];
    float4 b2 = t4[3L * i + 2];

    float r = giou_one(a0.x, a0.y, a0.z, a0.w, a1.x, a1.y,
                       b0.x, b0.y, b0.z, b0.w, b1.x, b1.y);
    r      += giou_one(a1.z, a1.w, a2.x, a2.y, a2.z, a2.w,
                       b1.z, b1.w, b2.x, b2.y, b2.z, b2.w);
    return r;
}

// Persistent one-wave CTAs pulling 512-pair chunks off a global ticket.
// Each chunk: 2 independent pairs/thread (12 front-batched LDG.128).
// Next ticket is fetched at chunk start so atomic latency hides under compute.
__global__ void __launch_bounds__(TPB) k_giou(
    const float4* __restrict__ p4, const float4* __restrict__ t4,
    int npairs, int nboxes, int nchunks, float* __restrict__ out)
{
    __shared__ unsigned int s_tick;
    __shared__ float        ws[8];
    __shared__ bool         is_last;

    float s = 0.0f;
    int lane = threadIdx.x & 31;
    int w    = threadIdx.x >> 5;

    // first ticket (exposed latency once)
    if (threadIdx.x == 0) s_tick = atomicAdd(&g_work, 1u);
    __syncthreads();
    unsigned int cur = s_tick;

    while (cur < (unsigned int)nchunks) {
        // issue next ticket now; consume after the barrier below
        unsigned int next_t = 0;
        if (threadIdx.x == 0) next_t = atomicAdd(&g_work, 1u);

        long base = (long)cur * CHUNK_PAIRS;
        long i0 = base + threadIdx.x;
        long i1 = i0 + TPB;
        if (i1 < npairs) {
            s += giou_pair(p4, t4, i0);
            s += giou_pair(p4, t4, i1);
        } else {
            if (i0 < npairs) s += giou_pair(p4, t4, i0);
        }

        __syncthreads();
        if (threadIdx.x == 0) s_tick = next_t;
        __syncthreads();
        cur = s_tick;
    }

    // odd tail box (not hit for N=4M, kept for generality)
    if ((nboxes & 1) && blockIdx.x == 0 && threadIdx.x == 0) {
        const float* pf = (const float*)p4;
        const float* tf = (const float*)t4;
        long b = (long)(nboxes - 1) * 6;
        s += giou_one(pf[b+0], pf[b+1], pf[b+2], pf[b+3], pf[b+4], pf[b+5],
                      tf[b+0], tf[b+1], tf[b+2], tf[b+3], tf[b+4], tf[b+5]);
    }

    // ---- block reduce (float) ----
    #pragma unroll
    for (int o = 16; o > 0; o >>= 1)
        s += __shfl_down_sync(0xffffffffu, s, o);

    if (lane == 0) ws[w] = s;
    __syncthreads();

    if (threadIdx.x == 0) {
        float bs = 0.0f;
        #pragma unroll
        for (int j = 0; j < 8; j++) bs += ws[j];
        g_part[blockIdx.x] = (double)bs;
        __threadfence();
        unsigned int t = atomicAdd(&g_count, 1u);
        is_last = (t == gridDim.x - 1);
    }
    __syncthreads();

    // ---- last block: final reduction, output, state reset ----
    if (is_last) {
        double d = 0.0;
        for (int j = threadIdx.x; j < gridDim.x; j += blockDim.x)
            d += g_part[j];

        #pragma unroll
        for (int o = 16; o > 0; o >>= 1)
            d += __shfl_down_sync(0xffffffffu, d, o);

        __shared__ double wd[8];
        if (lane == 0) wd[w] = d;
        __syncthreads();
        if (threadIdx.x == 0) {
            double tot = 0.0;
            #pragma unroll
            for (int j = 0; j < 8; j++) tot += wd[j];
            out[0] = (float)(-tot);   // loss = -sum(giou)
            g_count = 0;              // reset for next graph replay
            g_work  = 0;
        }
    }
}

extern "C" void kernel_launch(void* const* d_in, const int* in_sizes, int n_in,
                              void* d_out, int out_size)
{
    const float* pred = (const float*)d_in[0];
    const float* targ = (const float*)d_in[1];
    float* out = (float*)d_out;

    int nboxes  = in_sizes[0] / 6;
    int npairs  = nboxes / 2;
    int nchunks = (npairs + CHUNK_PAIRS - 1) / CHUNK_PAIRS;

    // Exact one wave: resident blocks/SM * SM count (host query, cached).
    static int blocks_cached = 0;
    if (blocks_cached == 0) {
        int maxb = 0;
        cudaOccupancyMaxActiveBlocksPerMultiprocessor(&maxb, k_giou, TPB, 0);
        if (maxb < 1) maxb = 4;
        int sms = 148;
        cudaDeviceGetAttribute(&sms, cudaDevAttrMultiProcessorCount, 0);
        long wv = (long)maxb * sms;
        blocks_cached = (wv > MAX_BLOCKS) ? MAX_BLOCKS : (int)wv;
    }
    int blocks = blocks_cached;
    if (blocks > nchunks) blocks = nchunks;
    if (blocks < 1) blocks = 1;

    k_giou<<<blocks, TPB>>>((const float4*)pred, (const float4*)targ,
                            npairs, nboxes, nchunks, out);
}